// round 1
// baseline (speedup 1.0000x reference)
#include <cuda_runtime.h>
#include <math.h>

#define NW 4
#define DIM 16
#define NK 81            // 3^4 Pauli strings {I,Z,Y}^4
#define BMAX 131072
#define EPS 1e-5

// ---- device globals (no allocations allowed) ----
__device__ float4 d_C[NK];          // coefficients [k][w]
__device__ double d_acc[8];         // sum q[w], sum q^2[w]
__device__ float4 d_qbuf[BMAX];     // per-element q (scratch)
__device__ float4 d_scale, d_shift; // batchnorm affine

// ============================================================
// Kernel 1: build W (16x16 unitary of the weighted layers) and
// the 324 polynomial coefficients C[w][k]. Also zero accumulators.
// ============================================================
__global__ void precompute_kernel(const float* __restrict__ weights) {
    __shared__ float2 W[DIM][DIM];   // W[p][col]
    int tid = threadIdx.x;

    if (tid < 8) d_acc[tid] = 0.0;

    if (tid < DIM) {
        int j = tid;
        float2 a[DIM];
#pragma unroll
        for (int i = 0; i < DIM; i++) a[i] = make_float2(i == j ? 1.f : 0.f, 0.f);

#pragma unroll
        for (int l = 0; l < 2; l++) {
#pragma unroll
            for (int w = 0; w < NW; w++) {
                float tx = weights[(l * NW + w) * 3 + 0];
                float ty = weights[(l * NW + w) * 3 + 1];
                float tz = weights[(l * NW + w) * 3 + 2];
                const int st = 1 << (3 - w);
                float c, s;
                // RX: [[c, -i s],[-i s, c]]
                sincosf(tx * 0.5f, &s, &c);
#pragma unroll
                for (int i = 0; i < DIM; i++) {
                    if (!(i & st)) {
                        float2 a0 = a[i], a1 = a[i | st];
                        a[i]      = make_float2(c * a0.x + s * a1.y, c * a0.y - s * a1.x);
                        a[i | st] = make_float2(s * a0.y + c * a1.x, -s * a0.x + c * a1.y);
                    }
                }
                // RY: [[c, -s],[s, c]]
                sincosf(ty * 0.5f, &s, &c);
#pragma unroll
                for (int i = 0; i < DIM; i++) {
                    if (!(i & st)) {
                        float2 a0 = a[i], a1 = a[i | st];
                        a[i]      = make_float2(c * a0.x - s * a1.x, c * a0.y - s * a1.y);
                        a[i | st] = make_float2(s * a0.x + c * a1.x, s * a0.y + c * a1.y);
                    }
                }
                // RZ: diag(e^{-it/2}, e^{+it/2})
                sincosf(tz * 0.5f, &s, &c);
#pragma unroll
                for (int i = 0; i < DIM; i++) {
                    if (!(i & st)) {
                        float2 a0 = a[i], a1 = a[i | st];
                        a[i]      = make_float2(c * a0.x + s * a0.y, c * a0.y - s * a0.x);
                        a[i | st] = make_float2(c * a1.x - s * a1.y, c * a1.y + s * a1.x);
                    }
                }
            }
            // ring of CNOTs: control w, target (w+1)%4; new[i] = old[perm[i]]
#pragma unroll
            for (int w = 0; w < NW; w++) {
                const int cm = 1 << (3 - w);
                const int tm = 1 << (3 - ((w + 1) & 3));
                float2 b[DIM];
#pragma unroll
                for (int i = 0; i < DIM; i++) {
                    int src = (i & cm) ? (i ^ tm) : i;
                    b[i] = a[src];
                }
#pragma unroll
                for (int i = 0; i < DIM; i++) a[i] = b[i];
            }
        }
#pragma unroll
        for (int p = 0; p < DIM; p++) W[p][j] = a[p];
    }
    __syncthreads();

    // C[w][k] = (1/16) Re[ (-i)^nY * sum_a r(a^m) * sum_p conj(W[p,a]) sgn_w(p) W[p,a^m] ]
    if (tid < NW * NK) {
        int w = tid / NK, k = tid % NK;
        int kd[4];
        { int kk = k; kd[3] = kk % 3; kk /= 3; kd[2] = kk % 3; kk /= 3; kd[1] = kk % 3; kd[0] = kk / 3; }
        int m = 0, nY = 0;
#pragma unroll
        for (int v = 0; v < 4; v++) if (kd[v] == 2) { m |= 1 << (3 - v); nY++; }

        float Tr = 0.f, Ti = 0.f;
        for (int a_ = 0; a_ < DIM; a_++) {
            int am = a_ ^ m;
            float r = 1.f;
#pragma unroll
            for (int v = 0; v < 4; v++)
                if (kd[v] != 0) r *= 1.f - 2.f * (float)((am >> (3 - v)) & 1);
            float sr = 0.f, si = 0.f;
            for (int p = 0; p < DIM; p++) {
                float sgn = ((p >> (3 - w)) & 1) ? -1.f : 1.f;
                float2 wa = W[p][a_], wb = W[p][am];
                sr += sgn * (wa.x * wb.x + wa.y * wb.y);   // Re(conj(wa)*wb)
                si += sgn * (wa.x * wb.y - wa.y * wb.x);   // Im(conj(wa)*wb)
            }
            Tr += r * sr;
            Ti += r * si;
        }
        float re;
        switch (nY & 3) {
            case 0: re = Tr; break;
            case 1: re = Ti; break;
            case 2: re = -Tr; break;
            default: re = -Ti; break;
        }
        ((float*)d_C)[k * 4 + w] = re * (1.f / 16.f);
    }
}

// ============================================================
// Kernel 2: pool + polynomial circuit eval + partial batch stats
// ============================================================
__global__ void __launch_bounds__(256) qcircuit_kernel(const float* __restrict__ x, int B) {
    __shared__ float4 Csh[NK];
    int tid = threadIdx.x;
    if (tid < NK) Csh[tid] = d_C[tid];
    __syncthreads();

    int b = blockIdx.x * blockDim.x + tid;
    float q0 = 0.f, q1 = 0.f, q2 = 0.f, q3 = 0.f;

    if (b < B) {
        const float4* xp = (const float4*)(x + (size_t)b * 144);
        float s0 = 0.f, s1 = 0.f, s2 = 0.f, s3 = 0.f;
#pragma unroll
        for (int r = 0; r < 12; r++) {
            float4 v0 = xp[r * 3 + 0];
            float4 v1 = xp[r * 3 + 1];
            float4 v2 = xp[r * 3 + 2];
            float left  = v0.x + v0.y + v0.z + v0.w + v1.x + v1.y;
            float right = v1.z + v1.w + v2.x + v2.y + v2.z + v2.w;
            if (r < 6) { s0 += left; s1 += right; }
            else       { s2 += left; s3 += right; }
        }
        const float inv36 = 1.f / 36.f;
        float t0 = s0 * inv36, t1 = s1 * inv36, t2 = s2 * inv36, t3 = s3 * inv36;
        float c0, c1, c2, c3, n0, n1, n2, n3;
        sincosf(t0, &n0, &c0);
        sincosf(t1, &n1, &c1);
        sincosf(t2, &n2, &c2);
        sincosf(t3, &n3, &c3);

        float g0[3] = {1.f, c0, -n0};
        float g1[3] = {1.f, c1, -n1};
        float g2[3] = {1.f, c2, -n2};
        float g3[3] = {1.f, c3, -n3};

#pragma unroll
        for (int k0 = 0; k0 < 3; k0++) {
            float a0 = g0[k0];
#pragma unroll
            for (int k1 = 0; k1 < 3; k1++) {
                float a1 = a0 * g1[k1];
#pragma unroll
                for (int k2 = 0; k2 < 3; k2++) {
                    float a2 = a1 * g2[k2];
#pragma unroll
                    for (int k3 = 0; k3 < 3; k3++) {
                        float a3 = a2 * g3[k3];
                        float4 cc = Csh[((k0 * 3 + k1) * 3 + k2) * 3 + k3];
                        q0 = fmaf(cc.x, a3, q0);
                        q1 = fmaf(cc.y, a3, q1);
                        q2 = fmaf(cc.z, a3, q2);
                        q3 = fmaf(cc.w, a3, q3);
                    }
                }
            }
        }
        d_qbuf[b] = make_float4(q0, q1, q2, q3);
    }

    // block reduction of sums and sums of squares (8 values)
    float v[8] = {q0, q1, q2, q3, q0 * q0, q1 * q1, q2 * q2, q3 * q3};
#pragma unroll
    for (int off = 16; off; off >>= 1) {
#pragma unroll
        for (int i = 0; i < 8; i++) v[i] += __shfl_xor_sync(0xffffffffu, v[i], off);
    }
    __shared__ float red[8][8];
    int warp = tid >> 5, lane = tid & 31;
    if (lane == 0) {
#pragma unroll
        for (int i = 0; i < 8; i++) red[i][warp] = v[i];
    }
    __syncthreads();
    if (tid == 0) {
        int nwarps = blockDim.x >> 5;
#pragma unroll
        for (int i = 0; i < 8; i++) {
            float t = 0.f;
            for (int wgi = 0; wgi < nwarps; wgi++) t += red[i][wgi];
            atomicAdd(&d_acc[i], (double)t);
        }
    }
}

// ============================================================
// Kernel 3: finalize batchnorm stats
// ============================================================
__global__ void finalize_kernel(const float* __restrict__ gamma,
                                const float* __restrict__ beta, int B) {
    int w = threadIdx.x;
    if (w < 4) {
        double mean = d_acc[w] / (double)B;
        double var  = d_acc[4 + w] / (double)B - mean * mean;
        double sc = (double)gamma[w] / sqrt(var + (double)EPS);
        double sh = (double)beta[w] - mean * sc;
        ((float*)&d_scale)[w] = (float)sc;
        ((float*)&d_shift)[w] = (float)sh;
    }
}

// ============================================================
// Kernel 4: apply normalization
// ============================================================
__global__ void __launch_bounds__(256) normalize_kernel(float* __restrict__ out, int B) {
    int i = blockIdx.x * blockDim.x + threadIdx.x;
    if (i < B) {
        float4 q = d_qbuf[i];
        float4 sc = d_scale, sh = d_shift;
        ((float4*)out)[i] = make_float4(fmaf(q.x, sc.x, sh.x),
                                        fmaf(q.y, sc.y, sh.y),
                                        fmaf(q.z, sc.z, sh.z),
                                        fmaf(q.w, sc.w, sh.w));
    }
}

extern "C" void kernel_launch(void* const* d_in, const int* in_sizes, int n_in,
                              void* d_out, int out_size) {
    const float* x       = (const float*)d_in[0];
    const float* weights = (const float*)d_in[1];
    const float* gamma   = (const float*)d_in[2];
    const float* beta    = (const float*)d_in[3];
    int B = in_sizes[0] / 144;
    if (B > BMAX) B = BMAX;

    precompute_kernel<<<1, 384>>>(weights);
    int threads = 256;
    int blocks = (B + threads - 1) / threads;
    qcircuit_kernel<<<blocks, threads>>>(x, B);
    finalize_kernel<<<1, 32>>>(gamma, beta, B);
    normalize_kernel<<<blocks, threads>>>((float*)d_out, B);
}